// round 5
// baseline (speedup 1.0000x reference)
#include <cuda_runtime.h>
#include <cuda.h>
#include <math.h>
#include <stdint.h>

// YOLO loss: preds [16384,7,7,30] f32, labels same, scalar f32 out.
// Warp-autonomous double-buffered pipeline:
//   512 blocks x 128 threads (4 warps). Each warp owns a private smem slice
//   (2 stages x [28 cells x 30 f32 preds | same labels] = 13440 B) and
//   streams its own cp.async groups. 28672 tiles of 28 cells; each of the
//   2048 warp-streams does exactly 14 tiles. No __syncthreads in the loop.
//   Block reduce + ticket atomic; last block reduces 512 partials in double.

#define SIDE 7
#define NBATCH 16384
#define NTHREADS 128
#define NWARPS 4
#define TILE_CELLS 28
#define TILE_FLOATS (TILE_CELLS * 30)        // 840
#define TILE4 (TILE_FLOATS / 4)              // 210 float4 per array
#define TILE_BYTES (TILE_FLOATS * 4)         // 3360 B per array
#define STAGE_BYTES (2 * TILE_BYTES)         // 6720 B (preds|labels)
#define WARP_BYTES (2 * STAGE_BYTES)         // 13440 B (2 stages)
#define SMEM_BYTES (NWARPS * WARP_BYTES)     // 53760 B
#define PGRID 512
#define NSTREAMS (PGRID * NWARPS)            // 2048
#define TILES_PER_STREAM 14                  // 28672 / 2048 exactly

__device__ float g_partials[PGRID];
__device__ unsigned int g_ticket = 0;

__device__ __forceinline__ void cp16(uint32_t smem_addr, const float4* gptr) {
    asm volatile("cp.async.cg.shared.global [%0], [%1], 16;\n"
                 :: "r"(smem_addr), "l"(gptr));
}

// Prefetch one 28-cell tile (210 float4 preds + 210 labels) into a stage.
__device__ __forceinline__ void prefetch_tile(uint32_t stage_base,
                                              const float4* __restrict__ p4,
                                              const float4* __restrict__ l4,
                                              int tile, int lane)
{
    const long long b = (long long)tile * TILE4;
    const float4* ps = p4 + b;
    const float4* ls = l4 + b;
    #pragma unroll
    for (int j = 0; j < 7; j++) {
        int i = lane + j * 32;
        if (i < TILE4) {
            cp16(stage_base + (uint32_t)i * 16u, ps + i);
            cp16(stage_base + (uint32_t)TILE_BYTES + (uint32_t)i * 16u, ls + i);
        }
    }
}

__device__ __forceinline__ float cell_loss(const float* __restrict__ p,
                                           const float* __restrict__ l)
{
    const float s = 1.0f / (float)SIDE;
    float conf = l[4];
    if (conf == 0.0f) {
        float d0 = p[4] - l[4];
        float d1 = p[9] - l[9];
        return 0.5f * (d0 * d0 + d1 * d1);
    }
    float l1x = l[0] * s - 0.5f * l[2];
    float l1y = l[1] * s - 0.5f * l[3];
    float l2x = l[0] * s + 0.5f * l[2];
    float l2y = l[1] * s + 0.5f * l[3];
    float la  = l[2] * l[3];

    float iou0, iou1;
    #pragma unroll
    for (int b = 0; b < 2; b++) {
        const float* pb = p + b * 5;
        float p1x = pb[0] * s - 0.5f * pb[2];
        float p1y = pb[1] * s - 0.5f * pb[3];
        float p2x = pb[0] * s + 0.5f * pb[2];
        float p2y = pb[1] * s + 0.5f * pb[3];
        float iw = fmaxf(fminf(p2x, l2x) - fmaxf(p1x, l1x), 0.0f);
        float ih = fmaxf(fminf(p2y, l2y) - fmaxf(p1y, l1y), 0.0f);
        float inter = iw * ih;
        float pa = pb[2] * pb[3];
        float v = inter / (pa + la - inter);
        if (b == 0) iou0 = v; else iou1 = v;
    }

    int idx = (iou1 > iou0) ? 1 : 0;   // jnp.argmax: first max wins
    float maxiou = fmaxf(iou0, iou1);

    const float* pr = p + idx * 5;
    const float* lr = l + idx * 5;

    float dresp = pr[4] - maxiou;
    float resp  = dresp * dresp;

    float nrc = p[(1 - idx) * 5 + 4];
    float nr  = nrc * nrc;

    float dx = pr[0] - lr[0];
    float dy = pr[1] - lr[1];
    float xy = dx * dx + dy * dy;

    float dw = sqrtf(pr[2]) - sqrtf(lr[2]);
    float dh = sqrtf(pr[3]) - sqrtf(lr[3]);
    float wh = dw * dw + dh * dh;

    float cls = 0.0f;
    #pragma unroll
    for (int k = 10; k < 30; k++) {
        float d = p[k] - l[k];
        cls += d * d;
    }

    return 5.0f * (xy + wh) + 2.0f * resp + nr + cls;
}

extern __shared__ char smem[];   // [4 warps][2 stages][preds 3360 | labels 3360]

__global__ __launch_bounds__(NTHREADS)
void yolo_warp_pipe_kernel(const float* __restrict__ preds,
                           const float* __restrict__ labels,
                           float* __restrict__ out)
{
    const int t    = threadIdx.x;
    const int lane = t & 31;
    const int wid  = t >> 5;

    const float4* p4 = (const float4*)preds;
    const float4* l4 = (const float4*)labels;

    const uint32_t warp_base =
        (uint32_t)__cvta_generic_to_shared(smem) + (uint32_t)wid * WARP_BYTES;
    const char* warp_gen = smem + wid * WARP_BYTES;

    const int gwid = blockIdx.x * NWARPS + wid;   // 0..2047

    float acc_cell = 0.0f;

    // Prologue: prefetch tile 0 into stage 0.
    prefetch_tile(warp_base, p4, l4, gwid, lane);
    asm volatile("cp.async.commit_group;\n" ::: "memory");

    #pragma unroll 1
    for (int i = 0; i < TILES_PER_STREAM; i++) {
        if (i + 1 < TILES_PER_STREAM) {
            prefetch_tile(warp_base + (uint32_t)((i + 1) & 1) * STAGE_BYTES,
                          p4, l4, gwid + (i + 1) * NSTREAMS, lane);
        }
        asm volatile("cp.async.commit_group;\n" ::: "memory");

        // All groups except the newest are done -> stage i&1 is ready
        // (once every lane has passed its own wait).
        asm volatile("cp.async.wait_group 1;\n" ::: "memory");
        __syncwarp();

        if (lane < TILE_CELLS) {
            const float* sp = (const float*)(warp_gen + (i & 1) * STAGE_BYTES);
            const float* sl = sp + TILE_FLOATS;
            acc_cell += cell_loss(sp + lane * 30, sl + lane * 30);
        }
        __syncwarp();   // all lanes done reading before this stage is refilled
    }

    // Block reduction: warp shuffle tree then cross-warp via smem.
    float v = acc_cell;
    #pragma unroll
    for (int off = 16; off > 0; off >>= 1)
        v += __shfl_down_sync(0xFFFFFFFFu, v, off);

    __shared__ float wsum[NWARPS];
    if (lane == 0) wsum[wid] = v;
    __syncthreads();

    __shared__ bool is_last;
    if (t == 0) {
        float bacc = 0.0f;
        #pragma unroll
        for (int w = 0; w < NWARPS; w++) bacc += wsum[w];
        g_partials[blockIdx.x] = bacc;
        __threadfence();
        unsigned int ticket = atomicAdd(&g_ticket, 1u);
        is_last = (ticket == PGRID - 1);
    }
    __syncthreads();

    // Last-arriving block: deterministic final reduction over 512 partials.
    if (is_last) {
        double acc = 0.0;
        #pragma unroll 1
        for (int i = t; i < PGRID; i += NTHREADS)
            acc += (double)g_partials[i];

        #pragma unroll
        for (int off = 16; off > 0; off >>= 1)
            acc += __shfl_down_sync(0xFFFFFFFFu, acc, off);

        __shared__ double dsum[NWARPS];
        if (lane == 0) dsum[wid] = acc;
        __syncthreads();

        if (t == 0) {
            double total = 0.0;
            #pragma unroll
            for (int w = 0; w < NWARPS; w++) total += dsum[w];
            out[0] = (float)(total / (double)NBATCH);
            g_ticket = 0;   // reset for next graph replay
        }
    }
}

extern "C" void kernel_launch(void* const* d_in, const int* in_sizes, int n_in,
                              void* d_out, int out_size)
{
    const float* preds  = (const float*)d_in[0];
    const float* labels = (const float*)d_in[1];
    float* out = (float*)d_out;

    static bool attr_set = false;
    if (!attr_set) {
        cudaFuncSetAttribute(yolo_warp_pipe_kernel,
                             cudaFuncAttributeMaxDynamicSharedMemorySize,
                             SMEM_BYTES);
        attr_set = true;
    }

    yolo_warp_pipe_kernel<<<PGRID, NTHREADS, SMEM_BYTES>>>(preds, labels, out);
}